// round 14
// baseline (speedup 1.0000x reference)
#include <cuda_runtime.h>
#include <cuda_bf16.h>
#include <math.h>

#define NN 4096
#define EE 131072
#define HIDD 64
#define OUTD 86
#define OUTP 88
#define BB 16
#define NHEADS 4
#define DH 16
#define CHUNKS 8
#define CKEYS (NN / CHUNKS)   // 512 keys per chunk
#define KT 128                // keys per smem tile
#define PREPB 1408            // prep blocks before the fused GCN1 gemm blocks

typedef unsigned int uint32;

__device__ __forceinline__ float ex2(float x) {
    float y; asm("ex2.approx.ftz.f32 %0,%1;" : "=f"(y) : "f"(x)); return y;
}
// pack two f32 -> bf16x2 (lo = first arg)
__device__ __forceinline__ uint32 packbf(float lo, float hi) {
    uint32 r; asm("cvt.rn.bf16x2.f32 %0, %1, %2;" : "=r"(r) : "f"(hi), "f"(lo)); return r;
}
__device__ __forceinline__ void mma16816(float* d, const uint32* a, uint32 b0, uint32 b1,
                                         const float* c) {
    asm("mma.sync.aligned.m16n8k16.row.col.f32.bf16.bf16.f32 "
        "{%0,%1,%2,%3},{%4,%5,%6,%7},{%8,%9},{%10,%11,%12,%13};"
        : "=f"(d[0]), "=f"(d[1]), "=f"(d[2]), "=f"(d[3])
        : "r"(a[0]), "r"(a[1]), "r"(a[2]), "r"(a[3]), "r"(b0), "r"(b1),
          "f"(c[0]), "f"(c[1]), "f"(c[2]), "f"(c[3]));
}

// ------------------------- scratch -----------------------------------------
__device__ float g_deg[NN];
__device__ float g_hw[NN * HIDD];
__device__ float g_agg1[NN * HIDD];
__device__ float g_qkv[NN * 3 * HIDD];
__device__ float g_h2w[NN * OUTP];
__device__ float g_agg2[NN * OUTP];
__device__ float g_pool[BB * OUTD];
__device__ float g_cnt[BB];
__device__ float g_pl[NHEADS * CHUNKS * NN];
__device__ float g_pacc[NHEADS * CHUNKS * NN * DH];
__device__ float g_Wc[OUTD * 64];
__device__ float g_bc[OUTD];

// ------------------------- prep: zero + folded weight + GCN1 GEMM ----------
// blocks [0,PREPB): zero/fold; blocks [PREPB, PREPB+256): hw = x @ W1^T
__global__ void __launch_bounds__(256) prep_kernel(const float* __restrict__ W2,
                                                   const float* __restrict__ Wout,
                                                   const float* __restrict__ b_out,
                                                   const float* __restrict__ x,
                                                   const float* __restrict__ W1) {
    int blk = blockIdx.x;
    int tid = threadIdx.x;
    if (blk < PREPB) {
        int idx = blk * 256 + tid;
        if (idx < NN * HIDD) g_agg1[idx] = 0.0f;
        if (idx < NN * OUTP) g_agg2[idx] = 0.0f;
        if (idx < BB * OUTD) g_pool[idx] = 0.0f;
        if (idx < BB) g_cnt[idx] = 0.0f;
        if (idx < NN) g_deg[idx] = 1.0f;   // self-loop weight 1
        if (idx < OUTD * 64) {             // Wc = W2 @ Wout ; bc = W2 @ b_out
            int r = idx >> 6, k = idx & 63;
            float s = 0.f;
#pragma unroll 8
            for (int c = 0; c < 64; c++) s = fmaf(W2[r * 64 + c], Wout[c * 64 + k], s);
            g_Wc[r * 64 + k] = s;
            if (k == 0) {
                float sb = 0.f;
#pragma unroll 8
                for (int c = 0; c < 64; c++) sb = fmaf(W2[r * 64 + c], b_out[c], sb);
                g_bc[r] = sb;
            }
        }
        return;
    }
    // ---- fused GCN1 linear (warp-per-2-rows, W prefetch) ----
    __shared__ __align__(16) float xsh[16][64];
    int lane = tid & 31;
    int warp = tid >> 5;
    int row0 = (blk - PREPB) * 16;
    {
        int r = tid >> 4, c4 = tid & 15;
        *(float4*)&xsh[r][c4 * 4] = *(const float4*)&x[(row0 + r) * 64 + c4 * 4];
    }
    __syncthreads();
    int r0 = warp * 2;
    float acc[2][2] = {{0.f, 0.f}, {0.f, 0.f}};
    float4 wb[2];
#pragma unroll
    for (int j = 0; j < 2; j++) wb[j] = *(const float4*)&W1[(lane + j * 32) * 64];
#pragma unroll
    for (int k4 = 0; k4 < 16; k4++) {
        float4 wc[2];
        wc[0] = wb[0]; wc[1] = wb[1];
        if (k4 < 15) {
#pragma unroll
            for (int j = 0; j < 2; j++)
                wb[j] = *(const float4*)&W1[(lane + j * 32) * 64 + (k4 + 1) * 4];
        }
        float4 xa = *(const float4*)&xsh[r0][k4 * 4];
        float4 xb = *(const float4*)&xsh[r0 + 1][k4 * 4];
#pragma unroll
        for (int j = 0; j < 2; j++) {
            acc[0][j] = fmaf(xa.x, wc[j].x, acc[0][j]); acc[0][j] = fmaf(xa.y, wc[j].y, acc[0][j]);
            acc[0][j] = fmaf(xa.z, wc[j].z, acc[0][j]); acc[0][j] = fmaf(xa.w, wc[j].w, acc[0][j]);
            acc[1][j] = fmaf(xb.x, wc[j].x, acc[1][j]); acc[1][j] = fmaf(xb.y, wc[j].y, acc[1][j]);
            acc[1][j] = fmaf(xb.z, wc[j].z, acc[1][j]); acc[1][j] = fmaf(xb.w, wc[j].w, acc[1][j]);
        }
    }
#pragma unroll
    for (int i = 0; i < 2; i++)
#pragma unroll
        for (int j = 0; j < 2; j++)
            g_hw[(row0 + r0 + i) * 64 + lane + j * 32] = acc[i][j];
}

__global__ void accum_kernel(const int* __restrict__ ei, const float* __restrict__ ea,
                             const int* __restrict__ batch) {
    int e = blockIdx.x * blockDim.x + threadIdx.x;
    if (e < EE) atomicAdd(&g_deg[ei[EE + e]], ea[e]);
    if (e < NN) atomicAdd(&g_cnt[batch[e]], 1.0f);
}

// ------------------------- GEMM (warp-per-2-rows, prefetch) -----------------
// MODE 1: fused GCN1-post, 2: fused attn-combine
template <int KOUT, int OST, bool BIAS, int MODE>
__global__ void __launch_bounds__(256) rowgemm(const float* __restrict__ W,
                                               const float* __restrict__ bias,
                                               const float* __restrict__ inb,
                                               float* __restrict__ out) {
    constexpr int CT = (KOUT + 31) / 32;
    __shared__ __align__(16) float xsh[16][64];
    int lane = threadIdx.x & 31;
    int warp = threadIdx.x >> 5;
    int row0 = blockIdx.x * 16;
    {
        int r = threadIdx.x >> 4, c4 = threadIdx.x & 15;
        int row = row0 + r;
        if (MODE == 1) {
            float d2 = __frcp_rn(g_deg[row]);
            float4 a  = *(const float4*)&g_agg1[row * 64 + c4 * 4];
            float4 hw = *(const float4*)&g_hw[row * 64 + c4 * 4];
            float4 bb = *(const float4*)&inb[c4 * 4];
            float4 v;
            v.x = fmaxf(fmaf(d2, hw.x, a.x) + bb.x, 0.f);
            v.y = fmaxf(fmaf(d2, hw.y, a.y) + bb.y, 0.f);
            v.z = fmaxf(fmaf(d2, hw.z, a.z) + bb.z, 0.f);
            v.w = fmaxf(fmaf(d2, hw.w, a.w) + bb.w, 0.f);
            *(float4*)&xsh[r][c4 * 4] = v;
        } else {
            int h = c4 >> 2, d0 = (c4 & 3) * 4;
            float l = 0.f;
            float4 o = make_float4(0.f, 0.f, 0.f, 0.f);
#pragma unroll
            for (int c = 0; c < CHUNKS; c++) {
                size_t idx = ((size_t)(h * CHUNKS + c)) * NN + row;
                l += g_pl[idx];
                float4 a = *(const float4*)&g_pacc[idx * DH + d0];
                o.x += a.x; o.y += a.y; o.z += a.z; o.w += a.w;
            }
            float inv = 1.0f / l;
            o.x *= inv; o.y *= inv; o.z *= inv; o.w *= inv;
            *(float4*)&xsh[r][c4 * 4] = o;
        }
    }
    __syncthreads();

    int r0 = warp * 2;
    float acc[2][CT];
#pragma unroll
    for (int i = 0; i < 2; i++)
#pragma unroll
        for (int j = 0; j < CT; j++) acc[i][j] = 0.0f;

    float4 wb[CT];
#pragma unroll
    for (int j = 0; j < CT; j++) {
        int c = lane + j * 32;
        wb[j] = ((KOUT & 31) == 0 || c < KOUT) ? *(const float4*)&W[c * 64]
                                               : make_float4(0.f, 0.f, 0.f, 0.f);
    }
#pragma unroll
    for (int k4 = 0; k4 < 16; k4++) {
        float4 wc[CT];
#pragma unroll
        for (int j = 0; j < CT; j++) wc[j] = wb[j];
        if (k4 < 15) {
#pragma unroll
            for (int j = 0; j < CT; j++) {
                int c = lane + j * 32;
                wb[j] = ((KOUT & 31) == 0 || c < KOUT)
                            ? *(const float4*)&W[c * 64 + (k4 + 1) * 4]
                            : make_float4(0.f, 0.f, 0.f, 0.f);
            }
        }
        float4 xa = *(const float4*)&xsh[r0][k4 * 4];
        float4 xb = *(const float4*)&xsh[r0 + 1][k4 * 4];
#pragma unroll
        for (int j = 0; j < CT; j++) {
            acc[0][j] = fmaf(xa.x, wc[j].x, acc[0][j]); acc[0][j] = fmaf(xa.y, wc[j].y, acc[0][j]);
            acc[0][j] = fmaf(xa.z, wc[j].z, acc[0][j]); acc[0][j] = fmaf(xa.w, wc[j].w, acc[0][j]);
            acc[1][j] = fmaf(xb.x, wc[j].x, acc[1][j]); acc[1][j] = fmaf(xb.y, wc[j].y, acc[1][j]);
            acc[1][j] = fmaf(xb.z, wc[j].z, acc[1][j]); acc[1][j] = fmaf(xb.w, wc[j].w, acc[1][j]);
        }
    }
#pragma unroll
    for (int i = 0; i < 2; i++) {
        int r = row0 + r0 + i;
#pragma unroll
        for (int j = 0; j < CT; j++) {
            int c = lane + j * 32;
            if ((KOUT & 31) == 0 || c < KOUT) {
                float v = acc[i][j];
                if (BIAS) v += bias[c];
                out[r * OST + c] = v;
            }
        }
    }
}

// ------------------------- GCN1 scatter: 16 lanes/edge, red.v4 -------------
__global__ void scatter64_kernel(const int* __restrict__ ei, const float* __restrict__ ea) {
    int gtid = blockIdx.x * blockDim.x + threadIdx.x;
    int e = gtid >> 4;
    if (e >= EE) return;
    int l16 = gtid & 15;
    int s = ei[e];
    int d = ei[EE + e];
    float coef = rsqrtf(g_deg[s]) * ea[e] * rsqrtf(g_deg[d]);
    float4 v = *(const float4*)&g_hw[s * 64 + l16 * 4];
    float* p = &g_agg1[d * 64 + l16 * 4];
    asm volatile("red.global.add.v4.f32 [%0], {%1,%2,%3,%4};"
                 :: "l"(p), "f"(coef * v.x), "f"(coef * v.y),
                    "f"(coef * v.z), "f"(coef * v.w) : "memory");
}

// ------------------------- attention: mma.sync bf16, split-K ---------------
// 256 queries/block (16 warps): staging amortized over 2x queries.
// grid (NN/256, NHEADS, CHUNKS), block 512.
__global__ void __launch_bounds__(512) attn_kernel() {
    int h = blockIdx.y, chunk = blockIdx.z;
    int lane = threadIdx.x & 31;
    int warp = threadIdx.x >> 5;          // 0..15
    int qbase = blockIdx.x * 256 + warp * 16;
    int g = lane >> 2, t4 = lane & 3;

    // K: [key][10 words], dim-pair p at word (p&3)*2 + (p>>2): frag pair adjacent
    __shared__ uint32 Ksh[KT * 10];
    // V: [dim][68 words]; key-pair w at 2*(w&3) + (w>>2) within 8-pair groups
    __shared__ uint32 Vt[16 * 68];

    const float SC = 0.25f * 1.44269504088896f;   // 1/sqrt(dh) * log2(e)
    uint32 qa[4];
    {
        const float* q0 = g_qkv + (qbase + g) * 192 + h * DH;
        const float* q1 = g_qkv + (qbase + g + 8) * 192 + h * DH;
        float2 v;
        v = *(const float2*)(q0 + 2 * t4);     qa[0] = packbf(v.x * SC, v.y * SC);
        v = *(const float2*)(q1 + 2 * t4);     qa[1] = packbf(v.x * SC, v.y * SC);
        v = *(const float2*)(q0 + 2 * t4 + 8); qa[2] = packbf(v.x * SC, v.y * SC);
        v = *(const float2*)(q1 + 2 * t4 + 8); qa[3] = packbf(v.x * SC, v.y * SC);
    }

    float o1[4] = {0.f, 0.f, 0.f, 0.f};
    float o2[4] = {0.f, 0.f, 0.f, 0.f};
    float lg = 0.f, lg8 = 0.f;
    const float zc[4] = {0.f, 0.f, 0.f, 0.f};

    for (int t = 0; t < CKEYS / KT; t++) {
        int key0 = chunk * CKEYS + t * KT;
        __syncthreads();
        for (int i = threadIdx.x; i < KT * 4; i += 512) {
            int j = i >> 2, c = i & 3;
            const float* base = g_qkv + (key0 + j) * 192 + 64 + h * DH + c * 4;
            float4 kv = *(const float4*)base;
            int p0 = 2 * c, p1 = 2 * c + 1;
            Ksh[j * 10 + (p0 & 3) * 2 + (p0 >> 2)] = packbf(kv.x, kv.y);
            Ksh[j * 10 + (p1 & 3) * 2 + (p1 >> 2)] = packbf(kv.z, kv.w);
            float4 vv = *(const float4*)(base + 64);
            int vidx = ((j >> 4) << 4) + (((j >> 1) & 3) << 2) + (((j >> 3) & 1) << 1) + (j & 1);
            __nv_bfloat16* vt = (__nv_bfloat16*)Vt;
            vt[(c * 4 + 0) * 136 + vidx] = __float2bfloat16(vv.x);
            vt[(c * 4 + 1) * 136 + vidx] = __float2bfloat16(vv.y);
            vt[(c * 4 + 2) * 136 + vidx] = __float2bfloat16(vv.z);
            vt[(c * 4 + 3) * 136 + vidx] = __float2bfloat16(vv.w);
        }
        __syncthreads();

#pragma unroll
        for (int kk = 0; kk < KT; kk += 16) {
            uint2 kb1 = *(const uint2*)&Ksh[(kk + g) * 10 + 2 * t4];
            uint2 kb2 = *(const uint2*)&Ksh[(kk + 8 + g) * 10 + 2 * t4];
            float s1[4], s2[4];
            mma16816(s1, qa, kb1.x, kb1.y, zc);
            mma16816(s2, qa, kb2.x, kb2.y, zc);
            s1[0] = ex2(s1[0]); s1[1] = ex2(s1[1]); s1[2] = ex2(s1[2]); s1[3] = ex2(s1[3]);
            s2[0] = ex2(s2[0]); s2[1] = ex2(s2[1]); s2[2] = ex2(s2[2]); s2[3] = ex2(s2[3]);
            lg  += (s1[0] + s1[1]) + (s2[0] + s2[1]);
            lg8 += (s1[2] + s1[3]) + (s2[2] + s2[3]);
            uint32 pa[4];
            pa[0] = packbf(s1[0], s1[1]);
            pa[1] = packbf(s1[2], s1[3]);
            pa[2] = packbf(s2[0], s2[1]);
            pa[3] = packbf(s2[2], s2[3]);
            int k2 = kk >> 1;
            uint2 vb1 = *(const uint2*)&Vt[g * 68 + k2 + 2 * t4];
            uint2 vb2 = *(const uint2*)&Vt[(g + 8) * 68 + k2 + 2 * t4];
            mma16816(o1, pa, vb1.x, vb1.y, o1);
            mma16816(o2, pa, vb2.x, vb2.y, o2);
        }
    }

    lg  += __shfl_xor_sync(0xFFFFFFFF, lg, 1);
    lg  += __shfl_xor_sync(0xFFFFFFFF, lg, 2);
    lg8 += __shfl_xor_sync(0xFFFFFFFF, lg8, 1);
    lg8 += __shfl_xor_sync(0xFFFFFFFF, lg8, 2);

    size_t base = ((size_t)(h * CHUNKS + chunk)) * NN;
    size_t idxA = base + qbase + g;
    size_t idxB = base + qbase + g + 8;
    *(float2*)&g_pacc[idxA * DH + 2 * t4]     = make_float2(o1[0], o1[1]);
    *(float2*)&g_pacc[idxA * DH + 8 + 2 * t4] = make_float2(o2[0], o2[1]);
    *(float2*)&g_pacc[idxB * DH + 2 * t4]     = make_float2(o1[2], o1[3]);
    *(float2*)&g_pacc[idxB * DH + 8 + 2 * t4] = make_float2(o2[2], o2[3]);
    if (t4 == 0) {
        g_pl[idxA] = lg;
        g_pl[idxB] = lg8;
    }
}

// ------------------------- GCN2 scatter: dense 22 lanes/edge ---------------
__global__ void scatter88_kernel(const int* __restrict__ ei, const float* __restrict__ ea) {
    int gtid = blockIdx.x * blockDim.x + threadIdx.x;
    int e = gtid / 22;
    if (e >= EE) return;
    int lane = gtid - e * 22;
    int s = ei[e];
    int d = ei[EE + e];
    float coef = rsqrtf(g_deg[s]) * ea[e] * rsqrtf(g_deg[d]);
    float4 v = *(const float4*)&g_h2w[s * OUTP + lane * 4];
    float* p = &g_agg2[d * OUTP + lane * 4];
    asm volatile("red.global.add.v4.f32 [%0], {%1,%2,%3,%4};"
                 :: "l"(p), "f"(coef * v.x), "f"(coef * v.y),
                    "f"(coef * v.z), "f"(coef * v.w) : "memory");
}

__global__ void final_node_kernel(const int* __restrict__ batch, const float* __restrict__ b2) {
    int idx = blockIdx.x * blockDim.x + threadIdx.x;
    if (idx >= NN * OUTP) return;
    int i = idx / OUTP, f = idx - i * OUTP;
    if (f >= OUTD) return;
    float d2 = __frcp_rn(g_deg[i]);
    float v = g_agg2[idx] + d2 * g_h2w[idx] + b2[f];
    atomicAdd(&g_pool[batch[i] * OUTD + f], v);
}

__global__ void out_kernel(float* __restrict__ out) {
    int idx = blockIdx.x * blockDim.x + threadIdx.x;
    if (idx >= BB * OUTD) return;
    int b = idx / OUTD;
    out[idx] = g_pool[idx] / fmaxf(g_cnt[b], 1.0f);
}

// ------------------------- launch ------------------------------------------
extern "C" void kernel_launch(void* const* d_in, const int* in_sizes, int n_in,
                              void* d_out, int out_size) {
    const float* x     = (const float*)d_in[0];
    const int*   ei    = (const int*)  d_in[1];
    const float* ea    = (const float*)d_in[2];
    const int*   batch = (const int*)  d_in[3];
    const float* W1    = (const float*)d_in[4];
    const float* b1    = (const float*)d_in[5];
    const float* Win   = (const float*)d_in[6];
    const float* b_in  = (const float*)d_in[7];
    const float* Wout  = (const float*)d_in[8];
    const float* b_out = (const float*)d_in[9];
    const float* W2    = (const float*)d_in[10];
    const float* b2    = (const float*)d_in[11];
    float* out = (float*)d_out;

    float *p_qkv, *p_h2w, *p_Wc, *p_bc;
    cudaGetSymbolAddress((void**)&p_qkv, g_qkv);
    cudaGetSymbolAddress((void**)&p_h2w, g_h2w);
    cudaGetSymbolAddress((void**)&p_Wc,  g_Wc);
    cudaGetSymbolAddress((void**)&p_bc,  g_bc);

    // 0. prep: zero accumulators + Wout fold + fused GCN1 GEMM
    prep_kernel<<<PREPB + NN / 16, 256>>>(W2, Wout, b_out, x, W1);
    // 1. degree + batch counts
    accum_kernel<<<EE / 256, 256>>>(ei, ea, batch);
    // 2. GCN1 aggregate (inline rsqrt norm)
    scatter64_kernel<<<EE * 16 / 256, 256>>>(ei, ea);
    // 3. QKV projection with fused GCN1 post
    rowgemm<192, 192, true, 1><<<NN / 16, 256>>>(Win, b_in, b1, p_qkv);
    // 4. attention (tensor-core split-K partials, 256 q/block)
    attn_kernel<<<dim3(NN / 256, NHEADS, CHUNKS), 512>>>();
    // 5. fused (Wout∘W2) linear with fused attention combine
    rowgemm<86, 88, true, 2><<<NN / 16, 256>>>(p_Wc, p_bc, nullptr, p_h2w);
    // 6. GCN2 aggregate + pool
    scatter88_kernel<<<EE * 22 / 256, 256>>>(ei, ea);
    final_node_kernel<<<(NN * OUTP + 255) / 256, 256>>>(batch, b2);
    out_kernel<<<(BB * OUTD + 255) / 256, 256>>>(out);
}

// round 15
// speedup vs baseline: 1.4294x; 1.4294x over previous
#include <cuda_runtime.h>
#include <cuda_bf16.h>
#include <math.h>

#define NN 4096
#define EE 131072
#define HIDD 64
#define OUTD 86
#define OUTP 88
#define BB 16
#define NHEADS 4
#define DH 16
#define CHUNKS 4
#define CKEYS (NN / CHUNKS)   // 1024 keys per chunk
#define KT 128                // keys per smem tile

typedef unsigned int uint32;

__device__ __forceinline__ float ex2(float x) {
    float y; asm("ex2.approx.ftz.f32 %0,%1;" : "=f"(y) : "f"(x)); return y;
}
// pack two f32 -> bf16x2 (lo = first arg)
__device__ __forceinline__ uint32 packbf(float lo, float hi) {
    uint32 r; asm("cvt.rn.bf16x2.f32 %0, %1, %2;" : "=r"(r) : "f"(hi), "f"(lo)); return r;
}
__device__ __forceinline__ void mma16816(float* d, const uint32* a, uint32 b0, uint32 b1,
                                         const float* c) {
    asm("mma.sync.aligned.m16n8k16.row.col.f32.bf16.bf16.f32 "
        "{%0,%1,%2,%3},{%4,%5,%6,%7},{%8,%9},{%10,%11,%12,%13};"
        : "=f"(d[0]), "=f"(d[1]), "=f"(d[2]), "=f"(d[3])
        : "r"(a[0]), "r"(a[1]), "r"(a[2]), "r"(a[3]), "r"(b0), "r"(b1),
          "f"(c[0]), "f"(c[1]), "f"(c[2]), "f"(c[3]));
}

// ------------------------- scratch -----------------------------------------
__device__ float g_deg[NN];
__device__ float g_hw[NN * HIDD];
__device__ float g_agg1[NN * HIDD];
__device__ float g_qkv[NN * 3 * HIDD];
__device__ float g_h2w[NN * OUTP];
__device__ float g_agg2[NN * OUTP];
__device__ float g_pool[BB * OUTD];
__device__ float g_cnt[BB];
__device__ float g_pl[NHEADS * CHUNKS * NN];
__device__ float g_pacc[NHEADS * CHUNKS * NN * DH];
__device__ float g_Wc[OUTD * 64];
__device__ float g_bc[OUTD];

// ------------------------- prep: zero + folded weight ----------------------
__global__ void prep_kernel(const float* __restrict__ W2, const float* __restrict__ Wout,
                            const float* __restrict__ b_out) {
    int idx = blockIdx.x * blockDim.x + threadIdx.x;
    if (idx < NN * HIDD) g_agg1[idx] = 0.0f;
    if (idx < NN * OUTP) g_agg2[idx] = 0.0f;
    if (idx < BB * OUTD) g_pool[idx] = 0.0f;
    if (idx < BB) g_cnt[idx] = 0.0f;
    if (idx < NN) g_deg[idx] = 1.0f;   // self-loop weight 1
    if (idx < OUTD * 64) {             // Wc = W2 @ Wout ; bc = W2 @ b_out
        int r = idx >> 6, k = idx & 63;
        float s = 0.f;
#pragma unroll 8
        for (int c = 0; c < 64; c++) s = fmaf(W2[r * 64 + c], Wout[c * 64 + k], s);
        g_Wc[r * 64 + k] = s;
        if (k == 0) {
            float sb = 0.f;
#pragma unroll 8
            for (int c = 0; c < 64; c++) sb = fmaf(W2[r * 64 + c], b_out[c], sb);
            g_bc[r] = sb;
        }
    }
}

__global__ void accum_kernel(const int* __restrict__ ei, const float* __restrict__ ea,
                             const int* __restrict__ batch) {
    int e = blockIdx.x * blockDim.x + threadIdx.x;
    if (e < EE) atomicAdd(&g_deg[ei[EE + e]], ea[e]);
    if (e < NN) atomicAdd(&g_cnt[batch[e]], 1.0f);
}

// ------------------------- GEMM: W staged in shared memory -----------------
// W in smem [c][68] (stride 68 -> conflict-free LDS.128 across lanes).
// MODE 0: plain input, 1: fused GCN1-post, 2: fused attn-combine
// block 256 (8 warps, warp-per-2-rows), 16 rows/block, grid NN/16.
template <int KOUT, int OST, bool BIAS, int MODE>
__global__ void __launch_bounds__(256) rowgemm(const float* __restrict__ in,
                                               const float* __restrict__ W,
                                               const float* __restrict__ bias,
                                               const float* __restrict__ inb,
                                               float* __restrict__ out) {
    constexpr int CT = (KOUT + 31) / 32;
    extern __shared__ __align__(16) float sm[];
    float* Wsh = sm;                   // [KOUT][68]
    float* xsh = sm + KOUT * 68;       // [16][64]
    int lane = threadIdx.x & 31;
    int warp = threadIdx.x >> 5;
    int row0 = blockIdx.x * 16;

    // stage W: float4 per element-group; Wsh[c*68 + k] = W[c*64 + k]
    for (int idx = threadIdx.x; idx < KOUT * 16; idx += 256) {
        int c = idx >> 4, k4 = idx & 15;
        *(float4*)&Wsh[c * 68 + k4 * 4] = *(const float4*)&W[c * 64 + k4 * 4];
    }
    // stage x (16 rows)
    {
        int r = threadIdx.x >> 4, c4 = threadIdx.x & 15;
        int row = row0 + r;
        if (MODE == 0) {
            *(float4*)&xsh[r * 64 + c4 * 4] = *(const float4*)&in[row * 64 + c4 * 4];
        } else if (MODE == 1) {
            float d2 = __frcp_rn(g_deg[row]);
            float4 a  = *(const float4*)&g_agg1[row * 64 + c4 * 4];
            float4 hw = *(const float4*)&g_hw[row * 64 + c4 * 4];
            float4 bb = *(const float4*)&inb[c4 * 4];
            float4 v;
            v.x = fmaxf(fmaf(d2, hw.x, a.x) + bb.x, 0.f);
            v.y = fmaxf(fmaf(d2, hw.y, a.y) + bb.y, 0.f);
            v.z = fmaxf(fmaf(d2, hw.z, a.z) + bb.z, 0.f);
            v.w = fmaxf(fmaf(d2, hw.w, a.w) + bb.w, 0.f);
            *(float4*)&xsh[r * 64 + c4 * 4] = v;
        } else {
            int h = c4 >> 2, d0 = (c4 & 3) * 4;
            float l = 0.f;
            float4 o = make_float4(0.f, 0.f, 0.f, 0.f);
#pragma unroll
            for (int c = 0; c < CHUNKS; c++) {
                size_t idx = ((size_t)(h * CHUNKS + c)) * NN + row;
                l += g_pl[idx];
                float4 a = *(const float4*)&g_pacc[idx * DH + d0];
                o.x += a.x; o.y += a.y; o.z += a.z; o.w += a.w;
            }
            float inv = 1.0f / l;
            o.x *= inv; o.y *= inv; o.z *= inv; o.w *= inv;
            *(float4*)&xsh[r * 64 + c4 * 4] = o;
        }
    }
    __syncthreads();

    int r0 = warp * 2;
    float acc[2][CT];
#pragma unroll
    for (int i = 0; i < 2; i++)
#pragma unroll
        for (int j = 0; j < CT; j++) acc[i][j] = 0.0f;

#pragma unroll
    for (int k4 = 0; k4 < 16; k4++) {
        float4 wc[CT];
#pragma unroll
        for (int j = 0; j < CT; j++) {
            int c = lane + j * 32;
            wc[j] = ((KOUT & 31) == 0 || c < KOUT)
                        ? *(const float4*)&Wsh[c * 68 + k4 * 4]
                        : make_float4(0.f, 0.f, 0.f, 0.f);
        }
        float4 xa = *(const float4*)&xsh[r0 * 64 + k4 * 4];
        float4 xb = *(const float4*)&xsh[(r0 + 1) * 64 + k4 * 4];
#pragma unroll
        for (int j = 0; j < CT; j++) {
            acc[0][j] = fmaf(xa.x, wc[j].x, acc[0][j]); acc[0][j] = fmaf(xa.y, wc[j].y, acc[0][j]);
            acc[0][j] = fmaf(xa.z, wc[j].z, acc[0][j]); acc[0][j] = fmaf(xa.w, wc[j].w, acc[0][j]);
            acc[1][j] = fmaf(xb.x, wc[j].x, acc[1][j]); acc[1][j] = fmaf(xb.y, wc[j].y, acc[1][j]);
            acc[1][j] = fmaf(xb.z, wc[j].z, acc[1][j]); acc[1][j] = fmaf(xb.w, wc[j].w, acc[1][j]);
        }
    }
#pragma unroll
    for (int i = 0; i < 2; i++) {
        int r = row0 + r0 + i;
#pragma unroll
        for (int j = 0; j < CT; j++) {
            int c = lane + j * 32;
            if ((KOUT & 31) == 0 || c < KOUT) {
                float v = acc[i][j];
                if (BIAS) v += bias[c];
                out[r * OST + c] = v;
            }
        }
    }
}

// ------------------------- GCN1 scatter: 16 lanes/edge, red.v4 -------------
__global__ void scatter64_kernel(const int* __restrict__ ei, const float* __restrict__ ea) {
    int gtid = blockIdx.x * blockDim.x + threadIdx.x;
    int e = gtid >> 4;
    if (e >= EE) return;
    int l16 = gtid & 15;
    int s = ei[e];
    int d = ei[EE + e];
    float coef = rsqrtf(g_deg[s]) * ea[e] * rsqrtf(g_deg[d]);
    float4 v = *(const float4*)&g_hw[s * 64 + l16 * 4];
    float* p = &g_agg1[d * 64 + l16 * 4];
    asm volatile("red.global.add.v4.f32 [%0], {%1,%2,%3,%4};"
                 :: "l"(p), "f"(coef * v.x), "f"(coef * v.y),
                    "f"(coef * v.z), "f"(coef * v.w) : "memory");
}

// ------------------------- attention: mma.sync bf16, split-K ---------------
// (r13 config: 128 q/block, 8 warps, CHUNKS=4, LDS.64 pair-interleaved layout)
__global__ void __launch_bounds__(256) attn_kernel() {
    int h = blockIdx.y, chunk = blockIdx.z;
    int lane = threadIdx.x & 31;
    int warp = threadIdx.x >> 5;
    int qbase = blockIdx.x * 128 + warp * 16;
    int g = lane >> 2, t4 = lane & 3;

    __shared__ uint32 Ksh[KT * 10];
    __shared__ uint32 Vt[16 * 68];

    const float SC = 0.25f * 1.44269504088896f;   // 1/sqrt(dh) * log2(e)
    uint32 qa[4];
    {
        const float* q0 = g_qkv + (qbase + g) * 192 + h * DH;
        const float* q1 = g_qkv + (qbase + g + 8) * 192 + h * DH;
        float2 v;
        v = *(const float2*)(q0 + 2 * t4);     qa[0] = packbf(v.x * SC, v.y * SC);
        v = *(const float2*)(q1 + 2 * t4);     qa[1] = packbf(v.x * SC, v.y * SC);
        v = *(const float2*)(q0 + 2 * t4 + 8); qa[2] = packbf(v.x * SC, v.y * SC);
        v = *(const float2*)(q1 + 2 * t4 + 8); qa[3] = packbf(v.x * SC, v.y * SC);
    }

    float o1[4] = {0.f, 0.f, 0.f, 0.f};
    float o2[4] = {0.f, 0.f, 0.f, 0.f};
    float lg = 0.f, lg8 = 0.f;
    const float zc[4] = {0.f, 0.f, 0.f, 0.f};

    for (int t = 0; t < CKEYS / KT; t++) {
        int key0 = chunk * CKEYS + t * KT;
        __syncthreads();
        for (int i = threadIdx.x; i < KT * 4; i += 256) {
            int j = i >> 2, c = i & 3;
            const float* base = g_qkv + (key0 + j) * 192 + 64 + h * DH + c * 4;
            float4 kv = *(const float4*)base;
            int p0 = 2 * c, p1 = 2 * c + 1;
            Ksh[j * 10 + (p0 & 3) * 2 + (p0 >> 2)] = packbf(kv.x, kv.y);
            Ksh[j * 10 + (p1 & 3) * 2 + (p1 >> 2)] = packbf(kv.z, kv.w);
            float4 vv = *(const float4*)(base + 64);
            int vidx = ((j >> 4) << 4) + (((j >> 1) & 3) << 2) + (((j >> 3) & 1) << 1) + (j & 1);
            __nv_bfloat16* vt = (__nv_bfloat16*)Vt;
            vt[(c * 4 + 0) * 136 + vidx] = __float2bfloat16(vv.x);
            vt[(c * 4 + 1) * 136 + vidx] = __float2bfloat16(vv.y);
            vt[(c * 4 + 2) * 136 + vidx] = __float2bfloat16(vv.z);
            vt[(c * 4 + 3) * 136 + vidx] = __float2bfloat16(vv.w);
        }
        __syncthreads();

#pragma unroll
        for (int kk = 0; kk < KT; kk += 16) {
            uint2 kb1 = *(const uint2*)&Ksh[(kk + g) * 10 + 2 * t4];
            uint2 kb2 = *(const uint2*)&Ksh[(kk + 8 + g) * 10 + 2 * t4];
            float s1[4], s2[4];
            mma16816(s1, qa, kb1.x, kb1.y, zc);
            mma16816(s2, qa, kb2.x, kb2.y, zc);
            s1[0] = ex2(s1[0]); s1[1] = ex2(s1[1]); s1[2] = ex2(s1[2]); s1[3] = ex2(s1[3]);
            s2[0] = ex2(s2[0]); s2[1] = ex2(s2[1]); s2[2] = ex2(s2[2]); s2[3] = ex2(s2[3]);
            lg  += (s1[0] + s1[1]) + (s2[0] + s2[1]);
            lg8 += (s1[2] + s1[3]) + (s2[2] + s2[3]);
            uint32 pa[4];
            pa[0] = packbf(s1[0], s1[1]);
            pa[1] = packbf(s1[2], s1[3]);
            pa[2] = packbf(s2[0], s2[1]);
            pa[3] = packbf(s2[2], s2[3]);
            int k2 = kk >> 1;
            uint2 vb1 = *(const uint2*)&Vt[g * 68 + k2 + 2 * t4];
            uint2 vb2 = *(const uint2*)&Vt[(g + 8) * 68 + k2 + 2 * t4];
            mma16816(o1, pa, vb1.x, vb1.y, o1);
            mma16816(o2, pa, vb2.x, vb2.y, o2);
        }
    }

    lg  += __shfl_xor_sync(0xFFFFFFFF, lg, 1);
    lg  += __shfl_xor_sync(0xFFFFFFFF, lg, 2);
    lg8 += __shfl_xor_sync(0xFFFFFFFF, lg8, 1);
    lg8 += __shfl_xor_sync(0xFFFFFFFF, lg8, 2);

    size_t base = ((size_t)(h * CHUNKS + chunk)) * NN;
    size_t idxA = base + qbase + g;
    size_t idxB = base + qbase + g + 8;
    *(float2*)&g_pacc[idxA * DH + 2 * t4]     = make_float2(o1[0], o1[1]);
    *(float2*)&g_pacc[idxA * DH + 8 + 2 * t4] = make_float2(o2[0], o2[1]);
    *(float2*)&g_pacc[idxB * DH + 2 * t4]     = make_float2(o1[2], o1[3]);
    *(float2*)&g_pacc[idxB * DH + 8 + 2 * t4] = make_float2(o2[2], o2[3]);
    if (t4 == 0) {
        g_pl[idxA] = lg;
        g_pl[idxB] = lg8;
    }
}

// ------------------------- GCN2 scatter: dense 22 lanes/edge ---------------
__global__ void scatter88_kernel(const int* __restrict__ ei, const float* __restrict__ ea) {
    int gtid = blockIdx.x * blockDim.x + threadIdx.x;
    int e = gtid / 22;
    if (e >= EE) return;
    int lane = gtid - e * 22;
    int s = ei[e];
    int d = ei[EE + e];
    float coef = rsqrtf(g_deg[s]) * ea[e] * rsqrtf(g_deg[d]);
    float4 v = *(const float4*)&g_h2w[s * OUTP + lane * 4];
    float* p = &g_agg2[d * OUTP + lane * 4];
    asm volatile("red.global.add.v4.f32 [%0], {%1,%2,%3,%4};"
                 :: "l"(p), "f"(coef * v.x), "f"(coef * v.y),
                    "f"(coef * v.z), "f"(coef * v.w) : "memory");
}

__global__ void final_node_kernel(const int* __restrict__ batch, const float* __restrict__ b2) {
    int idx = blockIdx.x * blockDim.x + threadIdx.x;
    if (idx >= NN * OUTP) return;
    int i = idx / OUTP, f = idx - i * OUTP;
    if (f >= OUTD) return;
    float d2 = __frcp_rn(g_deg[i]);
    float v = g_agg2[idx] + d2 * g_h2w[idx] + b2[f];
    atomicAdd(&g_pool[batch[i] * OUTD + f], v);
}

__global__ void out_kernel(float* __restrict__ out) {
    int idx = blockIdx.x * blockDim.x + threadIdx.x;
    if (idx >= BB * OUTD) return;
    int b = idx / OUTD;
    out[idx] = g_pool[idx] / fmaxf(g_cnt[b], 1.0f);
}

// ------------------------- launch ------------------------------------------
extern "C" void kernel_launch(void* const* d_in, const int* in_sizes, int n_in,
                              void* d_out, int out_size) {
    const float* x     = (const float*)d_in[0];
    const int*   ei    = (const int*)  d_in[1];
    const float* ea    = (const float*)d_in[2];
    const int*   batch = (const int*)  d_in[3];
    const float* W1    = (const float*)d_in[4];
    const float* b1    = (const float*)d_in[5];
    const float* Win   = (const float*)d_in[6];
    const float* b_in  = (const float*)d_in[7];
    const float* Wout  = (const float*)d_in[8];
    const float* b_out = (const float*)d_in[9];
    const float* W2    = (const float*)d_in[10];
    const float* b2    = (const float*)d_in[11];
    float* out = (float*)d_out;

    float *p_hw, *p_qkv, *p_h2w, *p_Wc, *p_bc;
    cudaGetSymbolAddress((void**)&p_hw,  g_hw);
    cudaGetSymbolAddress((void**)&p_qkv, g_qkv);
    cudaGetSymbolAddress((void**)&p_h2w, g_h2w);
    cudaGetSymbolAddress((void**)&p_Wc,  g_Wc);
    cudaGetSymbolAddress((void**)&p_bc,  g_bc);

    // dynamic smem: KOUT*68 + 16*64 floats
    const int smA = (64  * 68 + 16 * 64) * 4;   // 21504 B
    const int smB = (192 * 68 + 16 * 64) * 4;   // 56320 B
    const int smC = (86  * 68 + 16 * 64) * 4;   // 27488 B
    cudaFuncSetAttribute((const void*)rowgemm<192, 192, true, 1>,
                         cudaFuncAttributeMaxDynamicSharedMemorySize, smB);

    // 0. prep: zero accumulators + fold Wout into W2
    prep_kernel<<<(NN * OUTP + 255) / 256, 256>>>(W2, Wout, b_out);
    // 1. GCN1 linear
    rowgemm<64, 64, false, 0><<<NN / 16, 256, smA>>>(x, W1, nullptr, nullptr, p_hw);
    // 2. degree + batch counts
    accum_kernel<<<EE / 256, 256>>>(ei, ea, batch);
    // 3. GCN1 aggregate
    scatter64_kernel<<<EE * 16 / 256, 256>>>(ei, ea);
    // 4. QKV projection with fused GCN1 post
    rowgemm<192, 192, true, 1><<<NN / 16, 256, smB>>>(nullptr, Win, b_in, b1, p_qkv);
    // 5. attention (tensor-core split-K partials)
    attn_kernel<<<dim3(NN / 128, NHEADS, CHUNKS), 256>>>();
    // 6. fused (Wout∘W2) linear with fused attention combine
    rowgemm<86, 88, true, 2><<<NN / 16, 256, smC>>>(nullptr, p_Wc, p_bc, nullptr, p_h2w);
    // 7. GCN2 aggregate + pool
    scatter88_kernel<<<EE * 22 / 256, 256>>>(ei, ea);
    final_node_kernel<<<(NN * OUTP + 255) / 256, 256>>>(batch, b2);
    out_kernel<<<(BB * OUTD + 255) / 256, 256>>>(out);
}